// round 15
// baseline (speedup 1.0000x reference)
#include <cuda_runtime.h>
#include <cuda_bf16.h>
#include <math.h>
#include <stdint.h>

#define D 768
#define NH 12
#define DH 64
#define NMAX 8192
#define MAXE 64
#define NSPLIT 128
#define SLOWBLK 64

// fp32 scratch
__device__ float g_k[NMAX * D];
__device__ float g_v[NMAX * D];
__device__ float g_q[NMAX * D];
__device__ int g_idx[NMAX + 1];
__device__ unsigned char g_npad[NMAX];
__device__ int g_rank[NMAX];
__device__ int g_elist[MAXE];
__device__ int g_ne[1];
__device__ float g_part_ml[MAXE * NH * NSPLIT * 2];
__device__ float g_part_acc[MAXE * NH * NSPLIT * DH];

// bf16 hi/lo pre-split scratch
__device__ __nv_bfloat16 g_xqk_h[NMAX * D], g_xqk_l[NMAX * D];
__device__ __nv_bfloat16 g_xv_h[NMAX * D], g_xv_l[NMAX * D];
__device__ __nv_bfloat16 g_ctx_h[NMAX * D], g_ctx_l[NMAX * D];
__device__ __nv_bfloat16 g_wk_h[D * D], g_wk_l[D * D];
__device__ __nv_bfloat16 g_wv_h[D * D], g_wv_l[D * D];
__device__ __nv_bfloat16 g_wq_h[D * D], g_wq_l[D * D];
__device__ __nv_bfloat16 g_wo_h[D * D], g_wo_l[D * D];

// ---------------------------------------------------------------------------
__device__ __forceinline__ unsigned pack2(__nv_bfloat16 x, __nv_bfloat16 y) {
    __nv_bfloat162 t = __halves2bfloat162(x, y);
    return *reinterpret_cast<unsigned*>(&t);
}

__device__ __forceinline__ void split4(float4 v, uint2& hi, uint2& lo) {
    __nv_bfloat16 h0 = __float2bfloat16_rn(v.x);
    __nv_bfloat16 h1 = __float2bfloat16_rn(v.y);
    __nv_bfloat16 h2 = __float2bfloat16_rn(v.z);
    __nv_bfloat16 h3 = __float2bfloat16_rn(v.w);
    __nv_bfloat16 l0 = __float2bfloat16_rn(v.x - __bfloat162float(h0));
    __nv_bfloat16 l1 = __float2bfloat16_rn(v.y - __bfloat162float(h1));
    __nv_bfloat16 l2 = __float2bfloat16_rn(v.z - __bfloat162float(h2));
    __nv_bfloat16 l3 = __float2bfloat16_rn(v.w - __bfloat162float(h3));
    hi = make_uint2(pack2(h0, h1), pack2(h2, h3));
    lo = make_uint2(pack2(l0, l1), pack2(l2, l3));
}

__device__ __forceinline__ void store_split(__nv_bfloat16* h, __nv_bfloat16* l,
                                            size_t off, float v) {
    __nv_bfloat16 hh = __float2bfloat16_rn(v);
    h[off] = hh;
    l[off] = __float2bfloat16_rn(v - __bfloat162float(hh));
}

// ---------------------------------------------------------------------------
// merged split + prep: blocks [0, nsplit) do fp32->bf16 hi/lo split jobs;
// the LAST block does pad-mask + scan + empty-feature flags.
// ---------------------------------------------------------------------------
struct SplitJobs {
    const float4* src[6];
    uint2* hi[6];
    uint2* lo[6];
    int start[7];
};

struct PrepArgs {
    const int* qm;
    const int* ids_raw;
    const int* padp;
    int n, f;
    int* idxout;
    unsigned char* npad;
    int* rank;
    int* elist;
    int* ne;
};

__global__ void split_prep_kernel(SplitJobs J, PrepArgs P) {
    if ((int)blockIdx.x == (int)gridDim.x - 1) {
        __shared__ int cnts[256];
        __shared__ int pre[257];
        __shared__ int necnt;
        int t = threadIdx.x;
        int n = P.n, f = P.f;

        int pad = P.padp[0];
        bool is64 = (n > 1) && (P.ids_raw[1] == 0);
        for (int p = t; p < n; p += 256) {
            long long v = is64 ? ((const long long*)P.ids_raw)[p]
                               : (long long)P.ids_raw[p];
            P.npad[p] = (v != (long long)pad) ? 1 : 0;
        }

        int per = (n + 255) / 256;
        int s = t * per;
        int e = s + per; if (e > n) e = n;
        int c = 0;
        for (int p = s; p < e; p++) c += (P.qm[p] != 0);
        cnts[t] = c;
        __syncthreads();
        if (t == 0) {
            pre[0] = 0;
            for (int i = 0; i < 256; i++) pre[i + 1] = pre[i] + cnts[i];
            necnt = 0;
        }
        __syncthreads();
        int r = pre[t];
        for (int p = s; p < e; p++)
            if (P.qm[p] != 0) P.idxout[r++] = p;
        if (t == 0) P.idxout[f] = n;
        __syncthreads();

        for (int i = t; i < f; i += 256) {
            int L = P.idxout[i], R = P.idxout[i + 1];
            bool any = false;
            for (int p = L; p < R; p++) { if (P.npad[p]) { any = true; break; } }
            if (any) { P.rank[i] = -1; continue; }
            int rr = atomicAdd(&necnt, 1);
            P.rank[i] = rr;
            if (rr < MAXE) P.elist[rr] = i;
        }
        __syncthreads();
        if (t == 0) P.ne[0] = necnt;
        return;
    }
    int i = blockIdx.x * blockDim.x + threadIdx.x;
    if (i >= J.start[6]) return;
    int j = 0;
#pragma unroll
    for (int t = 1; t < 6; t++)
        if (i >= J.start[t]) j = t;
    int off = i - J.start[j];
    uint2 h, l;
    split4(J.src[j][off], h, l);
    J.hi[j][off] = h;
    J.lo[j][off] = l;
}

// ---------------------------------------------------------------------------
// Tensor-core NT GEMM on pre-split bf16 hi/lo operands (round-13 mainloop).
// ---------------------------------------------------------------------------
struct GArg {
    const __nv_bfloat16 *Ah, *Al, *Bh, *Bl;
    const float* bias;
    float* C;
    int M;
    const int* rowmap;
};

__device__ __forceinline__ void mma_bf16(float* d, const unsigned* a, const unsigned* b) {
    asm volatile(
        "mma.sync.aligned.m16n8k16.row.col.f32.bf16.bf16.f32 "
        "{%0,%1,%2,%3}, {%4,%5,%6,%7}, {%8,%9}, {%0,%1,%2,%3};\n"
        : "+f"(d[0]), "+f"(d[1]), "+f"(d[2]), "+f"(d[3])
        : "r"(a[0]), "r"(a[1]), "r"(a[2]), "r"(a[3]), "r"(b[0]), "r"(b[1]));
}

__device__ __forceinline__ void ldmx4(unsigned* r, unsigned saddr) {
    asm volatile(
        "ldmatrix.sync.aligned.m8n8.x4.shared.b16 {%0,%1,%2,%3}, [%4];\n"
        : "=r"(r[0]), "=r"(r[1]), "=r"(r[2]), "=r"(r[3]) : "r"(saddr));
}

__device__ __forceinline__ void cp_async16(void* dst, const void* src) {
    unsigned s = (unsigned)__cvta_generic_to_shared(dst);
    asm volatile("cp.async.cg.shared.global [%0], [%1], 16;\n" :: "r"(s), "l"(src));
}

template <int BM>
__global__ __launch_bounds__(256, 2)
void gemm_mma_bf(GArg g0, GArg g1, GArg g2, int N, int K) {
    const int WM = BM / 2;
    const int MT = WM / 16;
    const int STG_B = (BM + 128) * 128;
    extern __shared__ __align__(128) __nv_bfloat16 smraw[];

    GArg G = (blockIdx.z == 0) ? g0 : ((blockIdx.z == 1) ? g1 : g2);
    int M = G.M;
    int m0 = blockIdx.y * BM;
    if (m0 >= M) return;
    int n0 = blockIdx.x * 128;

    int tid = threadIdx.x;
    int warp = tid >> 5;
    int lane = tid & 31;
    int g = lane >> 2;
    int tig = lane & 3;
    int wm = warp >> 2;
    int wn = warp & 3;

    const int* rowmap = G.rowmap;

    float acc[MT][4][4];
#pragma unroll
    for (int i = 0; i < MT; i++)
#pragma unroll
        for (int j = 0; j < 4; j++)
#pragma unroll
            for (int r = 0; r < 4; r++) acc[i][j][r] = 0.f;

    auto load_stage = [&](int st, int k0) {
        char* base = (char*)smraw + st * STG_B;
#pragma unroll
        for (int c = tid; c < BM * 8; c += 256) {
            int r = c >> 3, ch = c & 7;
            int gr = m0 + r;
            if (gr >= M) gr = M - 1;
            int ar = rowmap ? rowmap[gr] : gr;
            size_t go = (size_t)ar * K + k0;
            const __nv_bfloat16* src = (ch < 4) ? (G.Ah + go + ch * 8)
                                                : (G.Al + go + (ch - 4) * 8);
            int dst = r * 128 + ((ch ^ (r & 7)) * 16);
            cp_async16(base + dst, src);
        }
#pragma unroll
        for (int c = tid; c < 128 * 8; c += 256) {
            int r = c >> 3, ch = c & 7;
            size_t go = (size_t)(n0 + r) * K + k0;
            const __nv_bfloat16* src = (ch < 4) ? (G.Bh + go + ch * 8)
                                                : (G.Bl + go + (ch - 4) * 8);
            int dst = BM * 128 + r * 128 + ((ch ^ (r & 7)) * 16);
            cp_async16(base + dst, src);
        }
        asm volatile("cp.async.commit_group;\n");
    };

    unsigned smem_u32 = (unsigned)__cvta_generic_to_shared(smraw);
    int apar = (lane & 16) ? 1 : 0;
    unsigned aoff[MT];
#pragma unroll
    for (int mt = 0; mt < MT; mt++) {
        int row = wm * WM + mt * 16 + (lane & 15);
        aoff[mt] = (unsigned)(row * 128 + ((apar ^ (row & 7)) * 16));
    }
    int brow = wn * 32 + ((lane & 16) ? 8 : 0) + (lane & 7);
    int bpar = (lane & 8) ? 1 : 0;
    unsigned boff = (unsigned)(BM * 128 + brow * 128 + ((bpar ^ (brow & 7)) * 16));

    int nk = K / 32;
    load_stage(0, 0);
    load_stage(1, 32);

    for (int i = 0; i < nk; i++) {
        if (i + 2 < nk) {
            asm volatile("cp.async.wait_group 1;\n");
        } else {
            asm volatile("cp.async.wait_group 0;\n");
        }
        __syncthreads();

        unsigned stb = smem_u32 + (unsigned)((i % 3) * STG_B);

#pragma unroll
        for (int ks = 0; ks < 2; ks++) {
            unsigned kx = ks << 5;
            unsigned bh[8], bl[8];
            ldmx4(&bh[0], stb + (boff ^ kx));
            ldmx4(&bh[4], stb + ((boff + 2048) ^ kx));
            ldmx4(&bl[0], stb + (boff ^ kx ^ 64));
            ldmx4(&bl[4], stb + ((boff + 2048) ^ kx ^ 64));
#pragma unroll
            for (int mt = 0; mt < MT; mt++) {
                unsigned ah[4], al[4];
                ldmx4(ah, stb + (aoff[mt] ^ kx));
                ldmx4(al, stb + (aoff[mt] ^ kx ^ 64));
#pragma unroll
                for (int nt = 0; nt < 4; nt++) mma_bf16(acc[mt][nt], ah, &bh[nt * 2]);
#pragma unroll
                for (int nt = 0; nt < 4; nt++) mma_bf16(acc[mt][nt], ah, &bl[nt * 2]);
#pragma unroll
                for (int nt = 0; nt < 4; nt++) mma_bf16(acc[mt][nt], al, &bh[nt * 2]);
            }
        }

        if (i + 2 < nk) load_stage((i + 2) % 3, (i + 2) * 32);
    }

#pragma unroll
    for (int mt = 0; mt < MT; mt++) {
#pragma unroll
        for (int nt = 0; nt < 4; nt++) {
            int row = m0 + wm * WM + mt * 16 + g;
            int col = n0 + wn * 32 + nt * 8 + 2 * tig;
            float b0 = G.bias[col], b1 = G.bias[col + 1];
            if (row < M) {
                float2 o = make_float2(acc[mt][nt][0] + b0, acc[mt][nt][1] + b1);
                *(float2*)(G.C + (size_t)row * N + col) = o;
            }
            if (row + 8 < M) {
                float2 o = make_float2(acc[mt][nt][2] + b0, acc[mt][nt][3] + b1);
                *(float2*)(G.C + (size_t)(row + 8) * N + col) = o;
            }
        }
    }
}

// ---------------------------------------------------------------------------
// FAST attention: one warp per (feature, head). Key-parallel, low-register.
// ---------------------------------------------------------------------------
__global__ __launch_bounds__(256)
void attn_fast_kernel(const float* __restrict__ q, const float* __restrict__ k,
                      const float* __restrict__ v, const int* __restrict__ idxarr,
                      const unsigned char* __restrict__ npad,
                      const int* __restrict__ rankarr,
                      __nv_bfloat16* __restrict__ ctx_h,
                      __nv_bfloat16* __restrict__ ctx_l, int ftot) {
    int warp = threadIdx.x >> 5;
    int lane = threadIdx.x & 31;
    int idx = blockIdx.x * 8 + warp;
    if (idx >= ftot * NH) return;
    int i = idx / NH;
    int h = idx - i * NH;

    int rk = rankarr[i];
    if (rk >= 0) return;
    int left = idxarr[i];
    int right = idxarr[i + 1];
    int nkeys = right - left;
    if (nkeys > 32) return;

    const float scale = 0.125f;
    int g4 = lane >> 2;
    int dg = lane & 3;
    const float* qb = q + (size_t)i * D + h * DH + dg * 16;
    float qv[16];
#pragma unroll
    for (int j = 0; j < 16; j += 4) {
        float4 t = *(const float4*)(qb + j);
        qv[j] = t.x; qv[j + 1] = t.y; qv[j + 2] = t.z; qv[j + 3] = t.w;
    }
    int nt = (nkeys + 7) >> 3;
    float sc[4], e[4];
    float m = -1e30f;
#pragma unroll
    for (int t = 0; t < 4; t++) {
        sc[t] = -1e30f;
        if (t < nt) {
            int kk = g4 + t * 8;
            int kc = kk < nkeys ? kk : (nkeys - 1);
            bool valid = (kk < nkeys) && npad[left + kc];
            const float* kb = k + (size_t)(left + kc) * D + h * DH + dg * 16;
            float part = 0.f;
#pragma unroll
            for (int j = 0; j < 16; j += 4) {
                float4 kv = *(const float4*)(kb + j);
                part += qv[j] * kv.x + qv[j + 1] * kv.y
                      + qv[j + 2] * kv.z + qv[j + 3] * kv.w;
            }
            part += __shfl_xor_sync(0xffffffffu, part, 1);
            part += __shfl_xor_sync(0xffffffffu, part, 2);
            sc[t] = valid ? part * scale : -1e30f;
        }
        m = fmaxf(m, sc[t]);
    }
    m = fmaxf(m, __shfl_xor_sync(0xffffffffu, m, 4));
    m = fmaxf(m, __shfl_xor_sync(0xffffffffu, m, 8));
    m = fmaxf(m, __shfl_xor_sync(0xffffffffu, m, 16));
    float lsum = 0.f;
#pragma unroll
    for (int t = 0; t < 4; t++) {
        e[t] = (sc[t] > -1e29f) ? __expf(sc[t] - m) : 0.f;
        lsum += e[t];
    }
    lsum += __shfl_xor_sync(0xffffffffu, lsum, 4);
    lsum += __shfl_xor_sync(0xffffffffu, lsum, 8);
    lsum += __shfl_xor_sync(0xffffffffu, lsum, 16);
    float inv = 1.0f / lsum;

    float a0 = 0.f, a1 = 0.f;
    for (int t = 0; t < nt; t++) {
        float v0r[8], v1r[8], w[8];
        int kmax = nkeys - t * 8; if (kmax > 8) kmax = 8;
#pragma unroll
        for (int kk = 0; kk < 8; kk++) {
            int key = kk < kmax ? kk : kmax - 1;
            const float* vb = v + (size_t)(left + t * 8 + key) * D + h * DH;
            v0r[kk] = vb[lane];
            v1r[kk] = vb[lane + 32];
            w[kk] = __shfl_sync(0xffffffffu, e[t], kk * 4);
        }
#pragma unroll
        for (int kk = 0; kk < 8; kk++) {
            if (kk < kmax) {
                a0 += w[kk] * v0r[kk];
                a1 += w[kk] * v1r[kk];
            }
        }
    }
    store_split(ctx_h, ctx_l, (size_t)i * D + h * DH + lane, a0 * inv);
    store_split(ctx_h, ctx_l, (size_t)i * D + h * DH + lane + 32, a1 * inv);
}

// ---------------------------------------------------------------------------
// SLOW attention safety net: PERSISTENT small grid; handles long segments
// (>32 keys) and empty-overflow. Warp-private q staging (no block syncs).
// ---------------------------------------------------------------------------
__global__ __launch_bounds__(NH * 32)
void attn_slow_kernel(const float* __restrict__ q, const float* __restrict__ k,
                      const float* __restrict__ v, const int* __restrict__ idxarr,
                      const unsigned char* __restrict__ npad,
                      const int* __restrict__ rankarr,
                      __nv_bfloat16* __restrict__ ctx_h,
                      __nv_bfloat16* __restrict__ ctx_l, int n, int f) {
    int h = threadIdx.x / 32;
    int lane = threadIdx.x % 32;
    const float scale = 0.125f;

    for (int i = blockIdx.x; i < f; i += SLOWBLK) {
        int rk = rankarr[i];
        int left = idxarr[i];
        int right = idxarr[i + 1];
        int nkeys = right - left;
        bool slow_seg = (rk < 0 && nkeys > 32);
        bool slow_empty = (rk >= MAXE);
        if (!slow_seg && !slow_empty) continue;

        const float* qb = q + (size_t)i * D + h * DH;
        float q0 = qb[lane];
        float q1 = qb[lane + 32];

        if (slow_seg) {
            float m = -1e30f;
            for (int p = left; p < right; p++) {
                if (!npad[p]) continue;
                const float* kb = k + (size_t)p * D + h * DH;
                float part = q0 * kb[lane] + q1 * kb[lane + 32];
#pragma unroll
                for (int o = 16; o > 0; o >>= 1) part += __shfl_xor_sync(0xffffffffu, part, o);
                float s = part * scale;
                if (s > m) m = s;
            }
            float l = 0.f, a0 = 0.f, a1 = 0.f;
            for (int p = left; p < right; p++) {
                if (!npad[p]) continue;
                const float* kb = k + (size_t)p * D + h * DH;
                float part = q0 * kb[lane] + q1 * kb[lane + 32];
#pragma unroll
                for (int o = 16; o > 0; o >>= 1) part += __shfl_xor_sync(0xffffffffu, part, o);
                float e = __expf(part * scale - m);
                const float* vb = v + (size_t)p * D + h * DH;
                l += e;
                a0 += e * vb[lane];
                a1 += e * vb[lane + 32];
            }
            store_split(ctx_h, ctx_l, (size_t)i * D + h * DH + lane, a0 / l);
            store_split(ctx_h, ctx_l, (size_t)i * D + h * DH + lane + 32, a1 / l);
        } else {
            // empty-overflow: full softmax over all n keys; lane-partitioned
            // online accumulation over DH via per-lane 2-dim slices.
            float m_i = -1e30f, l_i = 0.f;
            float acc0 = 0.f, acc1 = 0.f;
            // each lane owns dims {lane, lane+32}; scores computed cooperatively
            for (int p = 0; p < n; p++) {
                const float* kb = k + (size_t)p * D + h * DH;
                float part = q0 * kb[lane] + q1 * kb[lane + 32];
#pragma unroll
                for (int o = 16; o > 0; o >>= 1) part += __shfl_xor_sync(0xffffffffu, part, o);
                float s = part * scale;
                const float* vb = v + (size_t)p * D + h * DH;
                if (s > m_i) {
                    float c = __expf(m_i - s);
                    l_i = l_i * c + 1.0f;
                    acc0 = acc0 * c + vb[lane];
                    acc1 = acc1 * c + vb[lane + 32];
                    m_i = s;
                } else {
                    float e = __expf(s - m_i);
                    l_i += e;
                    acc0 += e * vb[lane];
                    acc1 += e * vb[lane + 32];
                }
            }
            store_split(ctx_h, ctx_l, (size_t)i * D + h * DH + lane, acc0 / l_i);
            store_split(ctx_h, ctx_l, (size_t)i * D + h * DH + lane + 32, acc1 / l_i);
        }
    }
}

// ---------------------------------------------------------------------------
// split-K flash decode for fully-masked features (branch-on-max online softmax)
// ---------------------------------------------------------------------------
__global__ __launch_bounds__(NH * 32)
void split_attn_kernel(const float* __restrict__ q, const float* __restrict__ k,
                       const float* __restrict__ v, const int* __restrict__ elist,
                       const int* __restrict__ nep,
                       float* __restrict__ part_ml, float* __restrict__ part_acc,
                       int n) {
    int split = blockIdx.x;
    int h = threadIdx.x / 32;
    int lane = threadIdx.x % 32;
    int ne = nep[0];
    if (ne > MAXE) ne = MAXE;
    if (ne == 0) return;
    int chunk = (n + NSPLIT - 1) / NSPLIT;
    int ks = split * chunk;
    int ke = ks + chunk; if (ke > n) ke = n;
    const float scale = 0.125f;

    for (int e0 = 0; e0 < ne; e0 += 8) {
        int gs = ne - e0; if (gs > 8) gs = 8;
        float q0[8], q1[8], m_[8], l_[8], a0[8], a1[8];
#pragma unroll
        for (int j = 0; j < 8; j++) {
            if (j < gs) {
                int ft = elist[e0 + j];
                q0[j] = q[(size_t)ft * D + h * DH + lane];
                q1[j] = q[(size_t)ft * D + h * DH + lane + 32];
            } else { q0[j] = 0.f; q1[j] = 0.f; }
            m_[j] = -1e30f; l_[j] = 0.f; a0[j] = 0.f; a1[j] = 0.f;
        }
        for (int p = ks; p < ke; p++) {
            const float* kb = k + (size_t)p * D + h * DH;
            const float* vb = v + (size_t)p * D + h * DH;
            float k0 = kb[lane], k1 = kb[lane + 32];
            float v0 = vb[lane], v1 = vb[lane + 32];
            float s[8];
#pragma unroll
            for (int j = 0; j < 8; j++) s[j] = q0[j] * k0 + q1[j] * k1;
#pragma unroll
            for (int o = 16; o > 0; o >>= 1)
#pragma unroll
                for (int j = 0; j < 8; j++) s[j] += __shfl_xor_sync(0xffffffffu, s[j], o);
#pragma unroll
            for (int j = 0; j < 8; j++) {
                float sc = s[j] * scale;
                if (sc > m_[j]) {
                    float corr = __expf(m_[j] - sc);
                    l_[j] = l_[j] * corr + 1.0f;
                    a0[j] = a0[j] * corr + v0;
                    a1[j] = a1[j] * corr + v1;
                    m_[j] = sc;
                } else {
                    float e = __expf(sc - m_[j]);
                    l_[j] += e;
                    a0[j] += e * v0;
                    a1[j] += e * v1;
                }
            }
        }
#pragma unroll
        for (int j = 0; j < 8; j++) {
            if (j >= gs) continue;
            size_t base = ((size_t)(e0 + j) * NH + h) * NSPLIT + split;
            if (lane == 0) { part_ml[base * 2] = m_[j]; part_ml[base * 2 + 1] = l_[j]; }
            part_acc[base * DH + lane] = a0[j];
            part_acc[base * DH + lane + 32] = a1[j];
        }
    }
}

__global__ __launch_bounds__(DH)
void reduce_attn_kernel(const int* __restrict__ elist, const int* __restrict__ nep,
                        const float* __restrict__ part_ml,
                        const float* __restrict__ part_acc,
                        __nv_bfloat16* __restrict__ ctx_h,
                        __nv_bfloat16* __restrict__ ctx_l) {
    int e = blockIdx.x, h = blockIdx.y;
    int ne = nep[0]; if (ne > MAXE) ne = MAXE;
    if (e >= ne) return;
    int d = threadIdx.x;
    __shared__ float wsh[NSPLIT];
    __shared__ float Lsh;
    if (d == 0) {
        float M = -1e30f;
        size_t mb = ((size_t)e * NH + h) * NSPLIT;
        for (int s = 0; s < NSPLIT; s++) {
            float m = part_ml[(mb + s) * 2];
            if (m > M) M = m;
        }
        float L = 0.f;
        for (int s = 0; s < NSPLIT; s++) {
            float m = part_ml[(mb + s) * 2];
            float l = part_ml[(mb + s) * 2 + 1];
            float w = __expf(m - M);
            wsh[s] = w;
            L += w * l;
        }
        Lsh = L;
    }
    __syncthreads();
    float acc = 0.f;
    size_t ab = ((size_t)e * NH + h) * NSPLIT;
    for (int s = 0; s < NSPLIT; s++) acc += wsh[s] * part_acc[(ab + s) * DH + d];
    int ft = elist[e];
    store_split(ctx_h, ctx_l, (size_t)ft * D + h * DH + d, acc / Lsh);
}

// ---------------------------------------------------------------------------
extern "C" void kernel_launch(void* const* d_in, const int* in_sizes, int n_in,
                              void* d_out, int out_size) {
    const float* x_qk = (const float*)d_in[0];
    const float* x_v = (const float*)d_in[1];
    const int* qm = (const int*)d_in[2];
    const int* ids = (const int*)d_in[3];
    const int* padp = (const int*)d_in[4];
    const float* Wq = (const float*)d_in[5];
    const float* bq = (const float*)d_in[6];
    const float* Wk = (const float*)d_in[7];
    const float* bk = (const float*)d_in[8];
    const float* Wv = (const float*)d_in[9];
    const float* bv = (const float*)d_in[10];
    const float* Wo = (const float*)d_in[11];
    const float* bo = (const float*)d_in[12];

    int n = in_sizes[0] / D;
    int f = out_size / D;

    float *pk, *pv, *pq, *pml, *pacc;
    int *pidx, *prank, *pelist, *pne;
    unsigned char* pnp;
    cudaGetSymbolAddress((void**)&pk, g_k);
    cudaGetSymbolAddress((void**)&pv, g_v);
    cudaGetSymbolAddress((void**)&pq, g_q);
    cudaGetSymbolAddress((void**)&pidx, g_idx);
    cudaGetSymbolAddress((void**)&pnp, g_npad);
    cudaGetSymbolAddress((void**)&prank, g_rank);
    cudaGetSymbolAddress((void**)&pelist, g_elist);
    cudaGetSymbolAddress((void**)&pne, g_ne);
    cudaGetSymbolAddress((void**)&pml, g_part_ml);
    cudaGetSymbolAddress((void**)&pacc, g_part_acc);

    __nv_bfloat16 *xqk_h, *xqk_l, *xv_h, *xv_l, *ctx_h, *ctx_l;
    __nv_bfloat16 *wk_h, *wk_l, *wv_h, *wv_l, *wq_h, *wq_l, *wo_h, *wo_l;
    cudaGetSymbolAddress((void**)&xqk_h, g_xqk_h);
    cudaGetSymbolAddress((void**)&xqk_l, g_xqk_l);
    cudaGetSymbolAddress((void**)&xv_h, g_xv_h);
    cudaGetSymbolAddress((void**)&xv_l, g_xv_l);
    cudaGetSymbolAddress((void**)&ctx_h, g_ctx_h);
    cudaGetSymbolAddress((void**)&ctx_l, g_ctx_l);
    cudaGetSymbolAddress((void**)&wk_h, g_wk_h);
    cudaGetSymbolAddress((void**)&wk_l, g_wk_l);
    cudaGetSymbolAddress((void**)&wv_h, g_wv_h);
    cudaGetSymbolAddress((void**)&wv_l, g_wv_l);
    cudaGetSymbolAddress((void**)&wq_h, g_wq_h);
    cudaGetSymbolAddress((void**)&wq_l, g_wq_l);
    cudaGetSymbolAddress((void**)&wo_h, g_wo_h);
    cudaGetSymbolAddress((void**)&wo_l, g_wo_l);

    // 1. merged pre-split + prep
    int nx4 = n * D / 4;
    int nw4 = D * D / 4;
    SplitJobs J;
    J.src[0] = (const float4*)x_qk; J.hi[0] = (uint2*)xqk_h; J.lo[0] = (uint2*)xqk_l;
    J.src[1] = (const float4*)x_v;  J.hi[1] = (uint2*)xv_h;  J.lo[1] = (uint2*)xv_l;
    J.src[2] = (const float4*)Wk;   J.hi[2] = (uint2*)wk_h;  J.lo[2] = (uint2*)wk_l;
    J.src[3] = (const float4*)Wv;   J.hi[3] = (uint2*)wv_h;  J.lo[3] = (uint2*)wv_l;
    J.src[4] = (const float4*)Wq;   J.hi[4] = (uint2*)wq_h;  J.lo[4] = (uint2*)wq_l;
    J.src[5] = (const float4*)Wo;   J.hi[5] = (uint2*)wo_h;  J.lo[5] = (uint2*)wo_l;
    J.start[0] = 0;
    J.start[1] = nx4;
    J.start[2] = 2 * nx4;
    J.start[3] = 2 * nx4 + nw4;
    J.start[4] = 2 * nx4 + 2 * nw4;
    J.start[5] = 2 * nx4 + 3 * nw4;
    J.start[6] = 2 * nx4 + 4 * nw4;
    PrepArgs P = {qm, ids, padp, n, f, pidx, pnp, prank, pelist, pne};
    int splitBlocks = (J.start[6] + 255) / 256;
    split_prep_kernel<<<splitBlocks + 1, 256>>>(J, P);

    // 2. fused K + V + Q GEMM
    const int smem128 = 3 * (128 + 128) * 128;  // 98304 B
    const int smem64 = 3 * (64 + 128) * 128;    // 73728 B
    cudaFuncSetAttribute(gemm_mma_bf<128>, cudaFuncAttributeMaxDynamicSharedMemorySize, smem128);
    cudaFuncSetAttribute(gemm_mma_bf<64>, cudaFuncAttributeMaxDynamicSharedMemorySize, smem64);
    GArg gK = {xqk_h, xqk_l, wk_h, wk_l, bk, pk, n, nullptr};
    GArg gV = {xv_h, xv_l, wv_h, wv_l, bv, pv, n, nullptr};
    GArg gQ = {xqk_h, xqk_l, wq_h, wq_l, bq, pq, f, pidx};
    gemm_mma_bf<128><<<dim3(D / 128, (n + 127) / 128, 3), 256, smem128>>>(gK, gV, gQ, D, D);

    // 3-6. attention (writes ctx bf16 hi/lo directly)
    attn_fast_kernel<<<(f * NH + 7) / 8, 256>>>(pq, pk, pv, pidx, pnp, prank,
                                                ctx_h, ctx_l, f);
    attn_slow_kernel<<<SLOWBLK, NH * 32>>>(pq, pk, pv, pidx, pnp, prank,
                                           ctx_h, ctx_l, n, f);
    split_attn_kernel<<<NSPLIT, NH * 32>>>(pq, pk, pv, pelist, pne, pml, pacc, n);
    reduce_attn_kernel<<<dim3(MAXE, NH), DH>>>(pelist, pne, pml, pacc, ctx_h, ctx_l);

    // 7. O GEMM
    GArg gO = {ctx_h, ctx_l, wo_h, wo_l, bo, (float*)d_out, f, nullptr};
    gemm_mma_bf<64><<<dim3(D / 128, (f + 63) / 64, 1), 256, smem64>>>(gO, gO, gO, D, D);
}

// round 16
// speedup vs baseline: 1.0481x; 1.0481x over previous
#include <cuda_runtime.h>
#include <cuda_bf16.h>
#include <math.h>
#include <stdint.h>

#define D 768
#define NH 12
#define DH 64
#define NMAX 8192
#define MAXE 64
#define NSPLIT 128

// fp32 scratch
__device__ float g_k[NMAX * D];
__device__ float g_v[NMAX * D];
__device__ float g_q[NMAX * D];
__device__ int g_idx[NMAX + 1];
__device__ unsigned char g_npad[NMAX];
__device__ int g_rank[NMAX];
__device__ int g_elist[MAXE];
__device__ int g_ne[1];
__device__ float g_part_ml[MAXE * NH * NSPLIT * 2];
__device__ float g_part_acc[MAXE * NH * NSPLIT * DH];

// bf16 hi/lo pre-split scratch
__device__ __nv_bfloat16 g_xqk_h[NMAX * D], g_xqk_l[NMAX * D];
__device__ __nv_bfloat16 g_xv_h[NMAX * D], g_xv_l[NMAX * D];
__device__ __nv_bfloat16 g_ctx_h[NMAX * D], g_ctx_l[NMAX * D];
__device__ __nv_bfloat16 g_wk_h[D * D], g_wk_l[D * D];
__device__ __nv_bfloat16 g_wv_h[D * D], g_wv_l[D * D];
__device__ __nv_bfloat16 g_wq_h[D * D], g_wq_l[D * D];
__device__ __nv_bfloat16 g_wo_h[D * D], g_wo_l[D * D];

// ---------------------------------------------------------------------------
__device__ __forceinline__ unsigned pack2(__nv_bfloat16 x, __nv_bfloat16 y) {
    __nv_bfloat162 t = __halves2bfloat162(x, y);
    return *reinterpret_cast<unsigned*>(&t);
}

__device__ __forceinline__ void split4(float4 v, uint2& hi, uint2& lo) {
    __nv_bfloat16 h0 = __float2bfloat16_rn(v.x);
    __nv_bfloat16 h1 = __float2bfloat16_rn(v.y);
    __nv_bfloat16 h2 = __float2bfloat16_rn(v.z);
    __nv_bfloat16 h3 = __float2bfloat16_rn(v.w);
    __nv_bfloat16 l0 = __float2bfloat16_rn(v.x - __bfloat162float(h0));
    __nv_bfloat16 l1 = __float2bfloat16_rn(v.y - __bfloat162float(h1));
    __nv_bfloat16 l2 = __float2bfloat16_rn(v.z - __bfloat162float(h2));
    __nv_bfloat16 l3 = __float2bfloat16_rn(v.w - __bfloat162float(h3));
    hi = make_uint2(pack2(h0, h1), pack2(h2, h3));
    lo = make_uint2(pack2(l0, l1), pack2(l2, l3));
}

__device__ __forceinline__ void store_split(__nv_bfloat16* h, __nv_bfloat16* l,
                                            size_t off, float v) {
    __nv_bfloat16 hh = __float2bfloat16_rn(v);
    h[off] = hh;
    l[off] = __float2bfloat16_rn(v - __bfloat162float(hh));
}

// merged multi-array split (6 jobs, one launch)
struct SplitJobs {
    const float4* src[6];
    uint2* hi[6];
    uint2* lo[6];
    int start[7];
};

__global__ void split_multi_kernel(SplitJobs J) {
    int i = blockIdx.x * blockDim.x + threadIdx.x;
    if (i >= J.start[6]) return;
    int j = 0;
#pragma unroll
    for (int t = 1; t < 6; t++)
        if (i >= J.start[t]) j = t;
    int off = i - J.start[j];
    uint2 h, l;
    split4(J.src[j][off], h, l);
    J.hi[j][off] = h;
    J.lo[j][off] = l;
}

// ---------------------------------------------------------------------------
// merged prep: pad mask + query-position scan + empty-feature flags
// ---------------------------------------------------------------------------
__global__ void prep_kernel(const int* __restrict__ qm,
                            const int* __restrict__ ids_raw,
                            const int* __restrict__ padp, int n, int f,
                            int* __restrict__ idxout,
                            unsigned char* __restrict__ npad,
                            int* __restrict__ rank, int* __restrict__ elist,
                            int* __restrict__ ne) {
    __shared__ int cnts[256];
    __shared__ int pre[257];
    __shared__ int necnt;
    int t = threadIdx.x;

    int pad = padp[0];
    bool is64 = (n > 1) && (ids_raw[1] == 0);
    for (int p = t; p < n; p += 256) {
        long long v = is64 ? ((const long long*)ids_raw)[p] : (long long)ids_raw[p];
        npad[p] = (v != (long long)pad) ? 1 : 0;
    }

    int per = (n + 255) / 256;
    int s = t * per;
    int e = s + per; if (e > n) e = n;
    int c = 0;
    for (int p = s; p < e; p++) c += (qm[p] != 0);
    cnts[t] = c;
    __syncthreads();
    if (t == 0) {
        pre[0] = 0;
        for (int i = 0; i < 256; i++) pre[i + 1] = pre[i] + cnts[i];
        necnt = 0;
    }
    __syncthreads();
    int r = pre[t];
    for (int p = s; p < e; p++)
        if (qm[p] != 0) idxout[r++] = p;
    if (t == 0) idxout[f] = n;
    __syncthreads();

    for (int i = t; i < f; i += 256) {
        int L = idxout[i], R = idxout[i + 1];
        bool any = false;
        for (int p = L; p < R; p++) { if (npad[p]) { any = true; break; } }
        if (any) { rank[i] = -1; continue; }
        int rr = atomicAdd(&necnt, 1);
        rank[i] = rr;
        if (rr < MAXE) elist[rr] = i;
    }
    __syncthreads();
    if (t == 0) ne[0] = necnt;
}

// ---------------------------------------------------------------------------
// Tensor-core NT GEMM on pre-split bf16 hi/lo operands (round-13 mainloop).
// SW128-swizzled smem, hi|lo packed per 128B row. 3-stage cp.async ring.
// ---------------------------------------------------------------------------
struct GArg {
    const __nv_bfloat16 *Ah, *Al, *Bh, *Bl;
    const float* bias;
    float* C;
    int M;
    const int* rowmap;
};

__device__ __forceinline__ void mma_bf16(float* d, const unsigned* a, const unsigned* b) {
    asm volatile(
        "mma.sync.aligned.m16n8k16.row.col.f32.bf16.bf16.f32 "
        "{%0,%1,%2,%3}, {%4,%5,%6,%7}, {%8,%9}, {%0,%1,%2,%3};\n"
        : "+f"(d[0]), "+f"(d[1]), "+f"(d[2]), "+f"(d[3])
        : "r"(a[0]), "r"(a[1]), "r"(a[2]), "r"(a[3]), "r"(b[0]), "r"(b[1]));
}

__device__ __forceinline__ void ldmx4(unsigned* r, unsigned saddr) {
    asm volatile(
        "ldmatrix.sync.aligned.m8n8.x4.shared.b16 {%0,%1,%2,%3}, [%4];\n"
        : "=r"(r[0]), "=r"(r[1]), "=r"(r[2]), "=r"(r[3]) : "r"(saddr));
}

__device__ __forceinline__ void cp_async16(void* dst, const void* src) {
    unsigned s = (unsigned)__cvta_generic_to_shared(dst);
    asm volatile("cp.async.cg.shared.global [%0], [%1], 16;\n" :: "r"(s), "l"(src));
}

template <int BM>
__global__ __launch_bounds__(256, 2)
void gemm_mma_bf(GArg g0, GArg g1, GArg g2, int N, int K) {
    const int WM = BM / 2;
    const int MT = WM / 16;
    const int STG_B = (BM + 128) * 128;
    extern __shared__ __align__(128) __nv_bfloat16 smraw[];

    GArg G = (blockIdx.z == 0) ? g0 : ((blockIdx.z == 1) ? g1 : g2);
    int M = G.M;
    int m0 = blockIdx.y * BM;
    if (m0 >= M) return;
    int n0 = blockIdx.x * 128;

    int tid = threadIdx.x;
    int warp = tid >> 5;
    int lane = tid & 31;
    int g = lane >> 2;
    int tig = lane & 3;
    int wm = warp >> 2;
    int wn = warp & 3;

    const int* rowmap = G.rowmap;

    float acc[MT][4][4];
#pragma unroll
    for (int i = 0; i < MT; i++)
#pragma unroll
        for (int j = 0; j < 4; j++)
#pragma unroll
            for (int r = 0; r < 4; r++) acc[i][j][r] = 0.f;

    auto load_stage = [&](int st, int k0) {
        char* base = (char*)smraw + st * STG_B;
#pragma unroll
        for (int c = tid; c < BM * 8; c += 256) {
            int r = c >> 3, ch = c & 7;
            int gr = m0 + r;
            if (gr >= M) gr = M - 1;
            int ar = rowmap ? rowmap[gr] : gr;
            size_t go = (size_t)ar * K + k0;
            const __nv_bfloat16* src = (ch < 4) ? (G.Ah + go + ch * 8)
                                                : (G.Al + go + (ch - 4) * 8);
            int dst = r * 128 + ((ch ^ (r & 7)) * 16);
            cp_async16(base + dst, src);
        }
#pragma unroll
        for (int c = tid; c < 128 * 8; c += 256) {
            int r = c >> 3, ch = c & 7;
            size_t go = (size_t)(n0 + r) * K + k0;
            const __nv_bfloat16* src = (ch < 4) ? (G.Bh + go + ch * 8)
                                                : (G.Bl + go + (ch - 4) * 8);
            int dst = BM * 128 + r * 128 + ((ch ^ (r & 7)) * 16);
            cp_async16(base + dst, src);
        }
        asm volatile("cp.async.commit_group;\n");
    };

    unsigned smem_u32 = (unsigned)__cvta_generic_to_shared(smraw);
    int apar = (lane & 16) ? 1 : 0;
    unsigned aoff[MT];
#pragma unroll
    for (int mt = 0; mt < MT; mt++) {
        int row = wm * WM + mt * 16 + (lane & 15);
        aoff[mt] = (unsigned)(row * 128 + ((apar ^ (row & 7)) * 16));
    }
    int brow = wn * 32 + ((lane & 16) ? 8 : 0) + (lane & 7);
    int bpar = (lane & 8) ? 1 : 0;
    unsigned boff = (unsigned)(BM * 128 + brow * 128 + ((bpar ^ (brow & 7)) * 16));

    int nk = K / 32;
    load_stage(0, 0);
    load_stage(1, 32);

    for (int i = 0; i < nk; i++) {
        if (i + 2 < nk) {
            asm volatile("cp.async.wait_group 1;\n");
        } else {
            asm volatile("cp.async.wait_group 0;\n");
        }
        __syncthreads();

        unsigned stb = smem_u32 + (unsigned)((i % 3) * STG_B);

#pragma unroll
        for (int ks = 0; ks < 2; ks++) {
            unsigned kx = ks << 5;
            unsigned bh[8], bl[8];
            ldmx4(&bh[0], stb + (boff ^ kx));
            ldmx4(&bh[4], stb + ((boff + 2048) ^ kx));
            ldmx4(&bl[0], stb + (boff ^ kx ^ 64));
            ldmx4(&bl[4], stb + ((boff + 2048) ^ kx ^ 64));
#pragma unroll
            for (int mt = 0; mt < MT; mt++) {
                unsigned ah[4], al[4];
                ldmx4(ah, stb + (aoff[mt] ^ kx));
                ldmx4(al, stb + (aoff[mt] ^ kx ^ 64));
#pragma unroll
                for (int nt = 0; nt < 4; nt++) mma_bf16(acc[mt][nt], ah, &bh[nt * 2]);
#pragma unroll
                for (int nt = 0; nt < 4; nt++) mma_bf16(acc[mt][nt], ah, &bl[nt * 2]);
#pragma unroll
                for (int nt = 0; nt < 4; nt++) mma_bf16(acc[mt][nt], al, &bh[nt * 2]);
            }
        }

        if (i + 2 < nk) load_stage((i + 2) % 3, (i + 2) * 32);
    }

#pragma unroll
    for (int mt = 0; mt < MT; mt++) {
#pragma unroll
        for (int nt = 0; nt < 4; nt++) {
            int row = m0 + wm * WM + mt * 16 + g;
            int col = n0 + wn * 32 + nt * 8 + 2 * tig;
            float b0 = G.bias[col], b1 = G.bias[col + 1];
            if (row < M) {
                float2 o = make_float2(acc[mt][nt][0] + b0, acc[mt][nt][1] + b1);
                *(float2*)(G.C + (size_t)row * N + col) = o;
            }
            if (row + 8 < M) {
                float2 o = make_float2(acc[mt][nt][2] + b0, acc[mt][nt][3] + b1);
                *(float2*)(G.C + (size_t)(row + 8) * N + col) = o;
            }
        }
    }
}

// ---------------------------------------------------------------------------
// Attention: one warp per (feature, head). Fast key-parallel path for
// segments <=32 keys; per-warp serial fallbacks for long segments and
// empty-overflow (never taken on this dataset, kept for correctness).
// ---------------------------------------------------------------------------
__global__ __launch_bounds__(256)
void attn_kernel(const float* __restrict__ q, const float* __restrict__ k,
                 const float* __restrict__ v, const int* __restrict__ idxarr,
                 const unsigned char* __restrict__ npad,
                 const int* __restrict__ rankarr,
                 __nv_bfloat16* __restrict__ ctx_h,
                 __nv_bfloat16* __restrict__ ctx_l, int n, int ftot) {
    int warp = threadIdx.x >> 5;
    int lane = threadIdx.x & 31;
    int idx = blockIdx.x * 8 + warp;
    if (idx >= ftot * NH) return;
    int i = idx / NH;
    int h = idx - i * NH;

    int rk = rankarr[i];
    if (rk >= 0 && rk < MAXE) return;  // empty features -> split path
    int left = idxarr[i];
    int right = idxarr[i + 1];
    int nkeys = right - left;
    const float scale = 0.125f;

    if (rk < 0 && nkeys <= 32) {
        // -------- fast key-parallel path --------
        int g4 = lane >> 2;
        int dg = lane & 3;
        const float* qb = q + (size_t)i * D + h * DH + dg * 16;
        float qv[16];
#pragma unroll
        for (int j = 0; j < 16; j += 4) {
            float4 t = *(const float4*)(qb + j);
            qv[j] = t.x; qv[j + 1] = t.y; qv[j + 2] = t.z; qv[j + 3] = t.w;
        }
        int nt = (nkeys + 7) >> 3;
        float sc[4], e[4];
        float m = -1e30f;
#pragma unroll
        for (int t = 0; t < 4; t++) {
            sc[t] = -1e30f;
            if (t < nt) {
                int kk = g4 + t * 8;
                int kc = kk < nkeys ? kk : (nkeys - 1);
                bool valid = (kk < nkeys) && npad[left + kc];
                const float* kb = k + (size_t)(left + kc) * D + h * DH + dg * 16;
                float part = 0.f;
#pragma unroll
                for (int j = 0; j < 16; j += 4) {
                    float4 kv = *(const float4*)(kb + j);
                    part += qv[j] * kv.x + qv[j + 1] * kv.y
                          + qv[j + 2] * kv.z + qv[j + 3] * kv.w;
                }
                part += __shfl_xor_sync(0xffffffffu, part, 1);
                part += __shfl_xor_sync(0xffffffffu, part, 2);
                sc[t] = valid ? part * scale : -1e30f;
            }
            m = fmaxf(m, sc[t]);
        }
        m = fmaxf(m, __shfl_xor_sync(0xffffffffu, m, 4));
        m = fmaxf(m, __shfl_xor_sync(0xffffffffu, m, 8));
        m = fmaxf(m, __shfl_xor_sync(0xffffffffu, m, 16));
        float lsum = 0.f;
#pragma unroll
        for (int t = 0; t < 4; t++) {
            e[t] = (sc[t] > -1e29f) ? __expf(sc[t] - m) : 0.f;
            lsum += e[t];
        }
        lsum += __shfl_xor_sync(0xffffffffu, lsum, 4);
        lsum += __shfl_xor_sync(0xffffffffu, lsum, 8);
        lsum += __shfl_xor_sync(0xffffffffu, lsum, 16);
        float inv = 1.0f / lsum;

        float a0 = 0.f, a1 = 0.f;
        for (int t = 0; t < nt; t++) {
            float v0r[8], v1r[8], w[8];
            int kmax = nkeys - t * 8; if (kmax > 8) kmax = 8;
#pragma unroll
            for (int kk = 0; kk < 8; kk++) {
                int key = kk < kmax ? kk : kmax - 1;
                const float* vb = v + (size_t)(left + t * 8 + key) * D + h * DH;
                v0r[kk] = vb[lane];
                v1r[kk] = vb[lane + 32];
                w[kk] = __shfl_sync(0xffffffffu, e[t], kk * 4);
            }
#pragma unroll
            for (int kk = 0; kk < 8; kk++) {
                if (kk < kmax) {
                    a0 += w[kk] * v0r[kk];
                    a1 += w[kk] * v1r[kk];
                }
            }
        }
        store_split(ctx_h, ctx_l, (size_t)i * D + h * DH + lane, a0 * inv);
        store_split(ctx_h, ctx_l, (size_t)i * D + h * DH + lane + 32, a1 * inv);
        return;
    }

    // -------- per-warp serial fallbacks (not taken on this dataset) --------
    const float* qb = q + (size_t)i * D + h * DH;
    float q0 = qb[lane];
    float q1 = qb[lane + 32];

    if (rk < 0) {
        // long segment: two-pass serial
        float m = -1e30f;
        for (int p = left; p < right; p++) {
            if (!npad[p]) continue;
            const float* kb = k + (size_t)p * D + h * DH;
            float part = q0 * kb[lane] + q1 * kb[lane + 32];
#pragma unroll
            for (int o = 16; o > 0; o >>= 1) part += __shfl_xor_sync(0xffffffffu, part, o);
            float s = part * scale;
            if (s > m) m = s;
        }
        float l = 0.f, a0 = 0.f, a1 = 0.f;
        for (int p = left; p < right; p++) {
            if (!npad[p]) continue;
            const float* kb = k + (size_t)p * D + h * DH;
            float part = q0 * kb[lane] + q1 * kb[lane + 32];
#pragma unroll
            for (int o = 16; o > 0; o >>= 1) part += __shfl_xor_sync(0xffffffffu, part, o);
            float e = __expf(part * scale - m);
            const float* vb = v + (size_t)p * D + h * DH;
            l += e;
            a0 += e * vb[lane];
            a1 += e * vb[lane + 32];
        }
        store_split(ctx_h, ctx_l, (size_t)i * D + h * DH + lane, a0 / l);
        store_split(ctx_h, ctx_l, (size_t)i * D + h * DH + lane + 32, a1 / l);
    } else {
        // empty-overflow (rk >= MAXE): full online softmax over all n keys
        float m_i = -1e30f, l_i = 0.f, acc0 = 0.f, acc1 = 0.f;
        for (int p = 0; p < n; p++) {
            const float* kb = k + (size_t)p * D + h * DH;
            float part = q0 * kb[lane] + q1 * kb[lane + 32];
#pragma unroll
            for (int o = 16; o > 0; o >>= 1) part += __shfl_xor_sync(0xffffffffu, part, o);
            float s = part * scale;
            const float* vb = v + (size_t)p * D + h * DH;
            if (s > m_i) {
                float c = __expf(m_i - s);
                l_i = l_i * c + 1.0f;
                acc0 = acc0 * c + vb[lane];
                acc1 = acc1 * c + vb[lane + 32];
                m_i = s;
            } else {
                float e = __expf(s - m_i);
                l_i += e;
                acc0 += e * vb[lane];
                acc1 += e * vb[lane + 32];
            }
        }
        store_split(ctx_h, ctx_l, (size_t)i * D + h * DH + lane, acc0 / l_i);
        store_split(ctx_h, ctx_l, (size_t)i * D + h * DH + lane + 32, acc1 / l_i);
    }
}

// ---------------------------------------------------------------------------
// split-K flash decode for fully-masked features (branch-on-max online softmax)
// ---------------------------------------------------------------------------
__global__ __launch_bounds__(NH * 32)
void split_attn_kernel(const float* __restrict__ q, const float* __restrict__ k,
                       const float* __restrict__ v, const int* __restrict__ elist,
                       const int* __restrict__ nep,
                       float* __restrict__ part_ml, float* __restrict__ part_acc,
                       int n) {
    int split = blockIdx.x;
    int h = threadIdx.x / 32;
    int lane = threadIdx.x % 32;
    int ne = nep[0];
    if (ne > MAXE) ne = MAXE;
    if (ne == 0) return;
    int chunk = (n + NSPLIT - 1) / NSPLIT;
    int ks = split * chunk;
    int ke = ks + chunk; if (ke > n) ke = n;
    const float scale = 0.125f;

    for (int e0 = 0; e0 < ne; e0 += 8) {
        int gs = ne - e0; if (gs > 8) gs = 8;
        float q0[8], q1[8], m_[8], l_[8], a0[8], a1[8];
#pragma unroll
        for (int j = 0; j < 8; j++) {
            if (j < gs) {
                int ft = elist[e0 + j];
                q0[j] = q[(size_t)ft * D + h * DH + lane];
                q1[j] = q[(size_t)ft * D + h * DH + lane + 32];
            } else { q0[j] = 0.f; q1[j] = 0.f; }
            m_[j] = -1e30f; l_[j] = 0.f; a0[j] = 0.f; a1[j] = 0.f;
        }
        for (int p = ks; p < ke; p++) {
            const float* kb = k + (size_t)p * D + h * DH;
            const float* vb = v + (size_t)p * D + h * DH;
            float k0 = kb[lane], k1 = kb[lane + 32];
            float v0 = vb[lane], v1 = vb[lane + 32];
            float s[8];
#pragma unroll
            for (int j = 0; j < 8; j++) s[j] = q0[j] * k0 + q1[j] * k1;
#pragma unroll
            for (int o = 16; o > 0; o >>= 1)
#pragma unroll
                for (int j = 0; j < 8; j++) s[j] += __shfl_xor_sync(0xffffffffu, s[j], o);
#pragma unroll
            for (int j = 0; j < 8; j++) {
                float sc = s[j] * scale;
                if (sc > m_[j]) {
                    float corr = __expf(m_[j] - sc);
                    l_[j] = l_[j] * corr + 1.0f;
                    a0[j] = a0[j] * corr + v0;
                    a1[j] = a1[j] * corr + v1;
                    m_[j] = sc;
                } else {
                    float e = __expf(sc - m_[j]);
                    l_[j] += e;
                    a0[j] += e * v0;
                    a1[j] += e * v1;
                }
            }
        }
#pragma unroll
        for (int j = 0; j < 8; j++) {
            if (j >= gs) continue;
            size_t base = ((size_t)(e0 + j) * NH + h) * NSPLIT + split;
            if (lane == 0) { part_ml[base * 2] = m_[j]; part_ml[base * 2 + 1] = l_[j]; }
            part_acc[base * DH + lane] = a0[j];
            part_acc[base * DH + lane + 32] = a1[j];
        }
    }
}

__global__ __launch_bounds__(DH)
void reduce_attn_kernel(const int* __restrict__ elist, const int* __restrict__ nep,
                        const float* __restrict__ part_ml,
                        const float* __restrict__ part_acc,
                        __nv_bfloat16* __restrict__ ctx_h,
                        __nv_bfloat16* __restrict__ ctx_l) {
    int e = blockIdx.x, h = blockIdx.y;
    int ne = nep[0]; if (ne > MAXE) ne = MAXE;
    if (e >= ne) return;
    int d = threadIdx.x;
    __shared__ float wsh[NSPLIT];
    __shared__ float Lsh;
    if (d == 0) {
        float M = -1e30f;
        size_t mb = ((size_t)e * NH + h) * NSPLIT;
        for (int s = 0; s < NSPLIT; s++) {
            float m = part_ml[(mb + s) * 2];
            if (m > M) M = m;
        }
        float L = 0.f;
        for (int s = 0; s < NSPLIT; s++) {
            float m = part_ml[(mb + s) * 2];
            float l = part_ml[(mb + s) * 2 + 1];
            float w = __expf(m - M);
            wsh[s] = w;
            L += w * l;
        }
        Lsh = L;
    }
    __syncthreads();
    float acc = 0.f;
    size_t ab = ((size_t)e * NH + h) * NSPLIT;
    for (int s = 0; s < NSPLIT; s++) acc += wsh[s] * part_acc[(ab + s) * DH + d];
    int ft = elist[e];
    store_split(ctx_h, ctx_l, (size_t)ft * D + h * DH + d, acc / Lsh);
}

// ---------------------------------------------------------------------------
extern "C" void kernel_launch(void* const* d_in, const int* in_sizes, int n_in,
                              void* d_out, int out_size) {
    const float* x_qk = (const float*)d_in[0];
    const float* x_v = (const float*)d_in[1];
    const int* qm = (const int*)d_in[2];
    const int* ids = (const int*)d_in[3];
    const int* padp = (const int*)d_in[4];
    const float* Wq = (const float*)d_in[5];
    const float* bq = (const float*)d_in[6];
    const float* Wk = (const float*)d_in[7];
    const float* bk = (const float*)d_in[8];
    const float* Wv = (const float*)d_in[9];
    const float* bv = (const float*)d_in[10];
    const float* Wo = (const float*)d_in[11];
    const float* bo = (const float*)d_in[12];

    int n = in_sizes[0] / D;
    int f = out_size / D;

    float *pk, *pv, *pq, *pml, *pacc;
    int *pidx, *prank, *pelist, *pne;
    unsigned char* pnp;
    cudaGetSymbolAddress((void**)&pk, g_k);
    cudaGetSymbolAddress((void**)&pv, g_v);
    cudaGetSymbolAddress((void**)&pq, g_q);
    cudaGetSymbolAddress((void**)&pidx, g_idx);
    cudaGetSymbolAddress((void**)&pnp, g_npad);
    cudaGetSymbolAddress((void**)&prank, g_rank);
    cudaGetSymbolAddress((void**)&pelist, g_elist);
    cudaGetSymbolAddress((void**)&pne, g_ne);
    cudaGetSymbolAddress((void**)&pml, g_part_ml);
    cudaGetSymbolAddress((void**)&pacc, g_part_acc);

    __nv_bfloat16 *xqk_h, *xqk_l, *xv_h, *xv_l, *ctx_h, *ctx_l;
    __nv_bfloat16 *wk_h, *wk_l, *wv_h, *wv_l, *wq_h, *wq_l, *wo_h, *wo_l;
    cudaGetSymbolAddress((void**)&xqk_h, g_xqk_h);
    cudaGetSymbolAddress((void**)&xqk_l, g_xqk_l);
    cudaGetSymbolAddress((void**)&xv_h, g_xv_h);
    cudaGetSymbolAddress((void**)&xv_l, g_xv_l);
    cudaGetSymbolAddress((void**)&ctx_h, g_ctx_h);
    cudaGetSymbolAddress((void**)&ctx_l, g_ctx_l);
    cudaGetSymbolAddress((void**)&wk_h, g_wk_h);
    cudaGetSymbolAddress((void**)&wk_l, g_wk_l);
    cudaGetSymbolAddress((void**)&wv_h, g_wv_h);
    cudaGetSymbolAddress((void**)&wv_l, g_wv_l);
    cudaGetSymbolAddress((void**)&wq_h, g_wq_h);
    cudaGetSymbolAddress((void**)&wq_l, g_wq_l);
    cudaGetSymbolAddress((void**)&wo_h, g_wo_h);
    cudaGetSymbolAddress((void**)&wo_l, g_wo_l);

    // 1. merged pre-split of inputs + weights
    int nx4 = n * D / 4;
    int nw4 = D * D / 4;
    SplitJobs J;
    J.src[0] = (const float4*)x_qk; J.hi[0] = (uint2*)xqk_h; J.lo[0] = (uint2*)xqk_l;
    J.src[1] = (const float4*)x_v;  J.hi[1] = (uint2*)xv_h;  J.lo[1] = (uint2*)xv_l;
    J.src[2] = (const float4*)Wk;   J.hi[2] = (uint2*)wk_h;  J.lo[2] = (uint2*)wk_l;
    J.src[3] = (const float4*)Wv;   J.hi[3] = (uint2*)wv_h;  J.lo[3] = (uint2*)wv_l;
    J.src[4] = (const float4*)Wq;   J.hi[4] = (uint2*)wq_h;  J.lo[4] = (uint2*)wq_l;
    J.src[5] = (const float4*)Wo;   J.hi[5] = (uint2*)wo_h;  J.lo[5] = (uint2*)wo_l;
    J.start[0] = 0;
    J.start[1] = nx4;
    J.start[2] = 2 * nx4;
    J.start[3] = 2 * nx4 + nw4;
    J.start[4] = 2 * nx4 + 2 * nw4;
    J.start[5] = 2 * nx4 + 3 * nw4;
    J.start[6] = 2 * nx4 + 4 * nw4;
    split_multi_kernel<<<(J.start[6] + 255) / 256, 256>>>(J);

    // 2. merged prep (mask + scan + empty flags)
    prep_kernel<<<1, 256>>>(qm, ids, padp, n, f, pidx, pnp, prank, pelist, pne);

    // 3. fused K + V + Q GEMM (swizzled compact smem)
    const int smem128 = 3 * (128 + 128) * 128;  // 98304 B
    const int smem64 = 3 * (64 + 128) * 128;    // 73728 B
    cudaFuncSetAttribute(gemm_mma_bf<128>, cudaFuncAttributeMaxDynamicSharedMemorySize, smem128);
    cudaFuncSetAttribute(gemm_mma_bf<64>, cudaFuncAttributeMaxDynamicSharedMemorySize, smem64);
    GArg gK = {xqk_h, xqk_l, wk_h, wk_l, bk, pk, n, nullptr};
    GArg gV = {xv_h, xv_l, wv_h, wv_l, bv, pv, n, nullptr};
    GArg gQ = {xqk_h, xqk_l, wq_h, wq_l, bq, pq, f, pidx};
    gemm_mma_bf<128><<<dim3(D / 128, (n + 127) / 128, 3), 256, smem128>>>(gK, gV, gQ, D, D);

    // 4-6. attention (single kernel handles fast + fallback paths)
    attn_kernel<<<(f * NH + 7) / 8, 256>>>(pq, pk, pv, pidx, pnp, prank,
                                           ctx_h, ctx_l, n, f);
    split_attn_kernel<<<NSPLIT, NH * 32>>>(pq, pk, pv, pelist, pne, pml, pacc, n);
    reduce_attn_kernel<<<dim3(MAXE, NH), DH>>>(pelist, pne, pml, pacc, ctx_h, ctx_l);

    // 7. O GEMM
    GArg gO = {ctx_h, ctx_l, wo_h, wo_l, bo, (float*)d_out, f, nullptr};
    gemm_mma_bf<64><<<dim3(D / 128, (f + 63) / 64, 1), 256, smem64>>>(gO, gO, gO, D, D);
}

// round 17
// speedup vs baseline: 1.0989x; 1.0485x over previous
#include <cuda_runtime.h>
#include <cuda_bf16.h>
#include <math.h>
#include <stdint.h>

#define D 768
#define NH 12
#define DH 64
#define NMAX 8192
#define MAXE 64
#define NSPLIT 128

// fp32 scratch
__device__ float g_k[NMAX * D];
__device__ float g_v[NMAX * D];
__device__ float g_q[NMAX * D];
__device__ int g_idx[NMAX + 1];
__device__ unsigned char g_npad[NMAX];
__device__ int g_rank[NMAX];
__device__ int g_elist[MAXE];
__device__ int g_ne[1];
__device__ float g_part_ml[MAXE * NH * NSPLIT * 2];
__device__ float g_part_acc[MAXE * NH * NSPLIT * DH];

// bf16 hi/lo pre-split scratch
__device__ __nv_bfloat16 g_xqk_h[NMAX * D], g_xqk_l[NMAX * D];
__device__ __nv_bfloat16 g_xv_h[NMAX * D], g_xv_l[NMAX * D];
__device__ __nv_bfloat16 g_ctx_h[NMAX * D], g_ctx_l[NMAX * D];
__device__ __nv_bfloat16 g_wk_h[D * D], g_wk_l[D * D];
__device__ __nv_bfloat16 g_wv_h[D * D], g_wv_l[D * D];
__device__ __nv_bfloat16 g_wq_h[D * D], g_wq_l[D * D];
__device__ __nv_bfloat16 g_wo_h[D * D], g_wo_l[D * D];

// ---------------------------------------------------------------------------
__device__ __forceinline__ unsigned pack2(__nv_bfloat16 x, __nv_bfloat16 y) {
    __nv_bfloat162 t = __halves2bfloat162(x, y);
    return *reinterpret_cast<unsigned*>(&t);
}

__device__ __forceinline__ void split4(float4 v, uint2& hi, uint2& lo) {
    __nv_bfloat16 h0 = __float2bfloat16_rn(v.x);
    __nv_bfloat16 h1 = __float2bfloat16_rn(v.y);
    __nv_bfloat16 h2 = __float2bfloat16_rn(v.z);
    __nv_bfloat16 h3 = __float2bfloat16_rn(v.w);
    __nv_bfloat16 l0 = __float2bfloat16_rn(v.x - __bfloat162float(h0));
    __nv_bfloat16 l1 = __float2bfloat16_rn(v.y - __bfloat162float(h1));
    __nv_bfloat16 l2 = __float2bfloat16_rn(v.z - __bfloat162float(h2));
    __nv_bfloat16 l3 = __float2bfloat16_rn(v.w - __bfloat162float(h3));
    hi = make_uint2(pack2(h0, h1), pack2(h2, h3));
    lo = make_uint2(pack2(l0, l1), pack2(l2, l3));
}

__device__ __forceinline__ void store_split(__nv_bfloat16* h, __nv_bfloat16* l,
                                            size_t off, float v) {
    __nv_bfloat16 hh = __float2bfloat16_rn(v);
    h[off] = hh;
    l[off] = __float2bfloat16_rn(v - __bfloat162float(hh));
}

// merged multi-array split (6 jobs, one launch)
struct SplitJobs {
    const float4* src[6];
    uint2* hi[6];
    uint2* lo[6];
    int start[7];
};

__global__ void split_multi_kernel(SplitJobs J) {
    int i = blockIdx.x * blockDim.x + threadIdx.x;
    if (i >= J.start[6]) return;
    int j = 0;
#pragma unroll
    for (int t = 1; t < 6; t++)
        if (i >= J.start[t]) j = t;
    int off = i - J.start[j];
    uint2 h, l;
    split4(J.src[j][off], h, l);
    J.hi[j][off] = h;
    J.lo[j][off] = l;
}

// ---------------------------------------------------------------------------
// merged prep: pad mask + query-position scan + empty-feature flags
// ---------------------------------------------------------------------------
__global__ void prep_kernel(const int* __restrict__ qm,
                            const int* __restrict__ ids_raw,
                            const int* __restrict__ padp, int n, int f,
                            int* __restrict__ idxout,
                            unsigned char* __restrict__ npad,
                            int* __restrict__ rank, int* __restrict__ elist,
                            int* __restrict__ ne) {
    __shared__ int cnts[256];
    __shared__ int pre[257];
    __shared__ int necnt;
    int t = threadIdx.x;

    int pad = padp[0];
    bool is64 = (n > 1) && (ids_raw[1] == 0);
    for (int p = t; p < n; p += 256) {
        long long v = is64 ? ((const long long*)ids_raw)[p] : (long long)ids_raw[p];
        npad[p] = (v != (long long)pad) ? 1 : 0;
    }

    int per = (n + 255) / 256;
    int s = t * per;
    int e = s + per; if (e > n) e = n;
    int c = 0;
    for (int p = s; p < e; p++) c += (qm[p] != 0);
    cnts[t] = c;
    __syncthreads();
    if (t == 0) {
        pre[0] = 0;
        for (int i = 0; i < 256; i++) pre[i + 1] = pre[i] + cnts[i];
        necnt = 0;
    }
    __syncthreads();
    int r = pre[t];
    for (int p = s; p < e; p++)
        if (qm[p] != 0) idxout[r++] = p;
    if (t == 0) idxout[f] = n;
    __syncthreads();

    for (int i = t; i < f; i += 256) {
        int L = idxout[i], R = idxout[i + 1];
        bool any = false;
        for (int p = L; p < R; p++) { if (npad[p]) { any = true; break; } }
        if (any) { rank[i] = -1; continue; }
        int rr = atomicAdd(&necnt, 1);
        rank[i] = rr;
        if (rr < MAXE) elist[rr] = i;
    }
    __syncthreads();
    if (t == 0) ne[0] = necnt;
}

// ---------------------------------------------------------------------------
// Tensor-core NT GEMM on pre-split bf16 hi/lo operands.
// SW128-swizzled smem, hi|lo packed per 128B row. 3-stage cp.async ring.
// ---------------------------------------------------------------------------
struct GArg {
    const __nv_bfloat16 *Ah, *Al, *Bh, *Bl;
    const float* bias;
    float* C;
    int M;
    const int* rowmap;
};

__device__ __forceinline__ void mma_bf16(float* d, const unsigned* a, const unsigned* b) {
    asm volatile(
        "mma.sync.aligned.m16n8k16.row.col.f32.bf16.bf16.f32 "
        "{%0,%1,%2,%3}, {%4,%5,%6,%7}, {%8,%9}, {%0,%1,%2,%3};\n"
        : "+f"(d[0]), "+f"(d[1]), "+f"(d[2]), "+f"(d[3])
        : "r"(a[0]), "r"(a[1]), "r"(a[2]), "r"(a[3]), "r"(b[0]), "r"(b[1]));
}

__device__ __forceinline__ void ldmx4(unsigned* r, unsigned saddr) {
    asm volatile(
        "ldmatrix.sync.aligned.m8n8.x4.shared.b16 {%0,%1,%2,%3}, [%4];\n"
        : "=r"(r[0]), "=r"(r[1]), "=r"(r[2]), "=r"(r[3]) : "r"(saddr));
}

__device__ __forceinline__ void cp_async16(void* dst, const void* src) {
    unsigned s = (unsigned)__cvta_generic_to_shared(dst);
    asm volatile("cp.async.cg.shared.global [%0], [%1], 16;\n" :: "r"(s), "l"(src));
}

template <int BM>
__global__ __launch_bounds__(256, 2)
void gemm_mma_bf(GArg g0, GArg g1, GArg g2, int N, int K) {
    const int WM = BM / 2;
    const int MT = WM / 16;
    const int STG_B = (BM + 128) * 128;
    extern __shared__ __align__(128) __nv_bfloat16 smraw[];

    GArg G = (blockIdx.z == 0) ? g0 : ((blockIdx.z == 1) ? g1 : g2);
    int M = G.M;
    int m0 = blockIdx.y * BM;
    if (m0 >= M) return;
    int n0 = blockIdx.x * 128;

    int tid = threadIdx.x;
    int warp = tid >> 5;
    int lane = tid & 31;
    int g = lane >> 2;
    int tig = lane & 3;
    int wm = warp >> 2;
    int wn = warp & 3;

    const int* rowmap = G.rowmap;

    float acc[MT][4][4];
#pragma unroll
    for (int i = 0; i < MT; i++)
#pragma unroll
        for (int j = 0; j < 4; j++)
#pragma unroll
            for (int r = 0; r < 4; r++) acc[i][j][r] = 0.f;

    auto load_stage = [&](int st, int k0) {
        char* base = (char*)smraw + st * STG_B;
#pragma unroll
        for (int c = tid; c < BM * 8; c += 256) {
            int r = c >> 3, ch = c & 7;
            int gr = m0 + r;
            if (gr >= M) gr = M - 1;
            int ar = rowmap ? rowmap[gr] : gr;
            size_t go = (size_t)ar * K + k0;
            const __nv_bfloat16* src = (ch < 4) ? (G.Ah + go + ch * 8)
                                                : (G.Al + go + (ch - 4) * 8);
            int dst = r * 128 + ((ch ^ (r & 7)) * 16);
            cp_async16(base + dst, src);
        }
#pragma unroll
        for (int c = tid; c < 128 * 8; c += 256) {
            int r = c >> 3, ch = c & 7;
            size_t go = (size_t)(n0 + r) * K + k0;
            const __nv_bfloat16* src = (ch < 4) ? (G.Bh + go + ch * 8)
                                                : (G.Bl + go + (ch - 4) * 8);
            int dst = BM * 128 + r * 128 + ((ch ^ (r & 7)) * 16);
            cp_async16(base + dst, src);
        }
        asm volatile("cp.async.commit_group;\n");
    };

    unsigned smem_u32 = (unsigned)__cvta_generic_to_shared(smraw);
    int apar = (lane & 16) ? 1 : 0;
    unsigned aoff[MT];
#pragma unroll
    for (int mt = 0; mt < MT; mt++) {
        int row = wm * WM + mt * 16 + (lane & 15);
        aoff[mt] = (unsigned)(row * 128 + ((apar ^ (row & 7)) * 16));
    }
    int brow = wn * 32 + ((lane & 16) ? 8 : 0) + (lane & 7);
    int bpar = (lane & 8) ? 1 : 0;
    unsigned boff = (unsigned)(BM * 128 + brow * 128 + ((bpar ^ (brow & 7)) * 16));

    int nk = K / 32;
    load_stage(0, 0);
    load_stage(1, 32);

    for (int i = 0; i < nk; i++) {
        if (i + 2 < nk) {
            asm volatile("cp.async.wait_group 1;\n");
        } else {
            asm volatile("cp.async.wait_group 0;\n");
        }
        __syncthreads();

        unsigned stb = smem_u32 + (unsigned)((i % 3) * STG_B);

#pragma unroll
        for (int ks = 0; ks < 2; ks++) {
            unsigned kx = ks << 5;
            unsigned bh[8], bl[8];
            ldmx4(&bh[0], stb + (boff ^ kx));
            ldmx4(&bh[4], stb + ((boff + 2048) ^ kx));
            ldmx4(&bl[0], stb + (boff ^ kx ^ 64));
            ldmx4(&bl[4], stb + ((boff + 2048) ^ kx ^ 64));
#pragma unroll
            for (int mt = 0; mt < MT; mt++) {
                unsigned ah[4], al[4];
                ldmx4(ah, stb + (aoff[mt] ^ kx));
                ldmx4(al, stb + (aoff[mt] ^ kx ^ 64));
#pragma unroll
                for (int nt = 0; nt < 4; nt++) mma_bf16(acc[mt][nt], ah, &bh[nt * 2]);
#pragma unroll
                for (int nt = 0; nt < 4; nt++) mma_bf16(acc[mt][nt], ah, &bl[nt * 2]);
#pragma unroll
                for (int nt = 0; nt < 4; nt++) mma_bf16(acc[mt][nt], al, &bh[nt * 2]);
            }
        }

        if (i + 2 < nk) load_stage((i + 2) % 3, (i + 2) * 32);
    }

#pragma unroll
    for (int mt = 0; mt < MT; mt++) {
#pragma unroll
        for (int nt = 0; nt < 4; nt++) {
            int row = m0 + wm * WM + mt * 16 + g;
            int col = n0 + wn * 32 + nt * 8 + 2 * tig;
            float b0 = G.bias[col], b1 = G.bias[col + 1];
            if (row < M) {
                float2 o = make_float2(acc[mt][nt][0] + b0, acc[mt][nt][1] + b1);
                *(float2*)(G.C + (size_t)row * N + col) = o;
            }
            if (row + 8 < M) {
                float2 o = make_float2(acc[mt][nt][2] + b0, acc[mt][nt][3] + b1);
                *(float2*)(G.C + (size_t)(row + 8) * N + col) = o;
            }
        }
    }
}

// ---------------------------------------------------------------------------
// Attention: one warp per (feature, head). Fast key-parallel path for
// segments <=32 keys; per-warp serial fallbacks otherwise.
// ---------------------------------------------------------------------------
__global__ __launch_bounds__(256)
void attn_kernel(const float* __restrict__ q, const float* __restrict__ k,
                 const float* __restrict__ v, const int* __restrict__ idxarr,
                 const unsigned char* __restrict__ npad,
                 const int* __restrict__ rankarr,
                 __nv_bfloat16* __restrict__ ctx_h,
                 __nv_bfloat16* __restrict__ ctx_l, int n, int ftot) {
    int warp = threadIdx.x >> 5;
    int lane = threadIdx.x & 31;
    int idx = blockIdx.x * 8 + warp;
    if (idx >= ftot * NH) return;
    int i = idx / NH;
    int h = idx - i * NH;

    int rk = rankarr[i];
    if (rk >= 0 && rk < MAXE) return;  // empty features -> split path
    int left = idxarr[i];
    int right = idxarr[i + 1];
    int nkeys = right - left;
    const float scale = 0.125f;

    if (rk < 0 && nkeys <= 32) {
        int g4 = lane >> 2;
        int dg = lane & 3;
        const float* qb = q + (size_t)i * D + h * DH + dg * 16;
        float qv[16];
#pragma unroll
        for (int j = 0; j < 16; j += 4) {
            float4 t = *(const float4*)(qb + j);
            qv[j] = t.x; qv[j + 1] = t.y; qv[j + 2] = t.z; qv[j + 3] = t.w;
        }
        int nt = (nkeys + 7) >> 3;
        float sc[4], e[4];
        float m = -1e30f;
#pragma unroll
        for (int t = 0; t < 4; t++) {
            sc[t] = -1e30f;
            if (t < nt) {
                int kk = g4 + t * 8;
                int kc = kk < nkeys ? kk : (nkeys - 1);
                bool valid = (kk < nkeys) && npad[left + kc];
                const float* kb = k + (size_t)(left + kc) * D + h * DH + dg * 16;
                float part = 0.f;
#pragma unroll
                for (int j = 0; j < 16; j += 4) {
                    float4 kv = *(const float4*)(kb + j);
                    part += qv[j] * kv.x + qv[j + 1] * kv.y
                          + qv[j + 2] * kv.z + qv[j + 3] * kv.w;
                }
                part += __shfl_xor_sync(0xffffffffu, part, 1);
                part += __shfl_xor_sync(0xffffffffu, part, 2);
                sc[t] = valid ? part * scale : -1e30f;
            }
            m = fmaxf(m, sc[t]);
        }
        m = fmaxf(m, __shfl_xor_sync(0xffffffffu, m, 4));
        m = fmaxf(m, __shfl_xor_sync(0xffffffffu, m, 8));
        m = fmaxf(m, __shfl_xor_sync(0xffffffffu, m, 16));
        float lsum = 0.f;
#pragma unroll
        for (int t = 0; t < 4; t++) {
            e[t] = (sc[t] > -1e29f) ? __expf(sc[t] - m) : 0.f;
            lsum += e[t];
        }
        lsum += __shfl_xor_sync(0xffffffffu, lsum, 4);
        lsum += __shfl_xor_sync(0xffffffffu, lsum, 8);
        lsum += __shfl_xor_sync(0xffffffffu, lsum, 16);
        float inv = 1.0f / lsum;

        float a0 = 0.f, a1 = 0.f;
        for (int t = 0; t < nt; t++) {
            float v0r[8], v1r[8], w[8];
            int kmax = nkeys - t * 8; if (kmax > 8) kmax = 8;
#pragma unroll
            for (int kk = 0; kk < 8; kk++) {
                int key = kk < kmax ? kk : kmax - 1;
                const float* vb = v + (size_t)(left + t * 8 + key) * D + h * DH;
                v0r[kk] = vb[lane];
                v1r[kk] = vb[lane + 32];
                w[kk] = __shfl_sync(0xffffffffu, e[t], kk * 4);
            }
#pragma unroll
            for (int kk = 0; kk < 8; kk++) {
                if (kk < kmax) {
                    a0 += w[kk] * v0r[kk];
                    a1 += w[kk] * v1r[kk];
                }
            }
        }
        store_split(ctx_h, ctx_l, (size_t)i * D + h * DH + lane, a0 * inv);
        store_split(ctx_h, ctx_l, (size_t)i * D + h * DH + lane + 32, a1 * inv);
        return;
    }

    // per-warp serial fallbacks (not taken on this dataset)
    const float* qb = q + (size_t)i * D + h * DH;
    float q0 = qb[lane];
    float q1 = qb[lane + 32];

    if (rk < 0) {
        float m = -1e30f;
        for (int p = left; p < right; p++) {
            if (!npad[p]) continue;
            const float* kb = k + (size_t)p * D + h * DH;
            float part = q0 * kb[lane] + q1 * kb[lane + 32];
#pragma unroll
            for (int o = 16; o > 0; o >>= 1) part += __shfl_xor_sync(0xffffffffu, part, o);
            float s = part * scale;
            if (s > m) m = s;
        }
        float l = 0.f, a0 = 0.f, a1 = 0.f;
        for (int p = left; p < right; p++) {
            if (!npad[p]) continue;
            const float* kb = k + (size_t)p * D + h * DH;
            float part = q0 * kb[lane] + q1 * kb[lane + 32];
#pragma unroll
            for (int o = 16; o > 0; o >>= 1) part += __shfl_xor_sync(0xffffffffu, part, o);
            float e = __expf(part * scale - m);
            const float* vb = v + (size_t)p * D + h * DH;
            l += e;
            a0 += e * vb[lane];
            a1 += e * vb[lane + 32];
        }
        store_split(ctx_h, ctx_l, (size_t)i * D + h * DH + lane, a0 / l);
        store_split(ctx_h, ctx_l, (size_t)i * D + h * DH + lane + 32, a1 / l);
    } else {
        float m_i = -1e30f, l_i = 0.f, acc0 = 0.f, acc1 = 0.f;
        for (int p = 0; p < n; p++) {
            const float* kb = k + (size_t)p * D + h * DH;
            float part = q0 * kb[lane] + q1 * kb[lane + 32];
#pragma unroll
            for (int o = 16; o > 0; o >>= 1) part += __shfl_xor_sync(0xffffffffu, part, o);
            float s = part * scale;
            const float* vb = v + (size_t)p * D + h * DH;
            if (s > m_i) {
                float c = __expf(m_i - s);
                l_i = l_i * c + 1.0f;
                acc0 = acc0 * c + vb[lane];
                acc1 = acc1 * c + vb[lane + 32];
                m_i = s;
            } else {
                float e = __expf(s - m_i);
                l_i += e;
                acc0 += e * vb[lane];
                acc1 += e * vb[lane + 32];
            }
        }
        store_split(ctx_h, ctx_l, (size_t)i * D + h * DH + lane, acc0 / l_i);
        store_split(ctx_h, ctx_l, (size_t)i * D + h * DH + lane + 32, acc1 / l_i);
    }
}

// ---------------------------------------------------------------------------
// split-K flash decode for fully-masked features (branch-on-max online softmax)
// ---------------------------------------------------------------------------
__global__ __launch_bounds__(NH * 32)
void split_attn_kernel(const float* __restrict__ q, const float* __restrict__ k,
                       const float* __restrict__ v, const int* __restrict__ elist,
                       const int* __restrict__ nep,
                       float* __restrict__ part_ml, float* __restrict__ part_acc,
                       int n) {
    int split = blockIdx.x;
    int h = threadIdx.x / 32;
    int lane = threadIdx.x % 32;
    int ne = nep[0];
    if (ne > MAXE) ne = MAXE;
    if (ne == 0) return;
    int chunk = (n + NSPLIT - 1) / NSPLIT;
    int ks = split * chunk;
    int ke = ks + chunk; if (ke > n) ke = n;
    const float scale = 0.125f;

    for (int e0 = 0; e0 < ne; e0 += 8) {
        int gs = ne - e0; if (gs > 8) gs = 8;
        float q0[8], q1[8], m_[8], l_[8], a0[8], a1[8];
#pragma unroll
        for (int j = 0; j < 8; j++) {
            if (j < gs) {
                int ft = elist[e0 + j];
                q0[j] = q[(size_t)ft * D + h * DH + lane];
                q1[j] = q[(size_t)ft * D + h * DH + lane + 32];
            } else { q0[j] = 0.f; q1[j] = 0.f; }
            m_[j] = -1e30f; l_[j] = 0.f; a0[j] = 0.f; a1[j] = 0.f;
        }
        for (int p = ks; p < ke; p++) {
            const float* kb = k + (size_t)p * D + h * DH;
            const float* vb = v + (size_t)p * D + h * DH;
            float k0 = kb[lane], k1 = kb[lane + 32];
            float v0 = vb[lane], v1 = vb[lane + 32];
            float s[8];
#pragma unroll
            for (int j = 0; j < 8; j++) s[j] = q0[j] * k0 + q1[j] * k1;
#pragma unroll
            for (int o = 16; o > 0; o >>= 1)
#pragma unroll
                for (int j = 0; j < 8; j++) s[j] += __shfl_xor_sync(0xffffffffu, s[j], o);
#pragma unroll
            for (int j = 0; j < 8; j++) {
                float sc = s[j] * scale;
                if (sc > m_[j]) {
                    float corr = __expf(m_[j] - sc);
                    l_[j] = l_[j] * corr + 1.0f;
                    a0[j] = a0[j] * corr + v0;
                    a1[j] = a1[j] * corr + v1;
                    m_[j] = sc;
                } else {
                    float e = __expf(sc - m_[j]);
                    l_[j] += e;
                    a0[j] += e * v0;
                    a1[j] += e * v1;
                }
            }
        }
#pragma unroll
        for (int j = 0; j < 8; j++) {
            if (j >= gs) continue;
            size_t base = ((size_t)(e0 + j) * NH + h) * NSPLIT + split;
            if (lane == 0) { part_ml[base * 2] = m_[j]; part_ml[base * 2 + 1] = l_[j]; }
            part_acc[base * DH + lane] = a0[j];
            part_acc[base * DH + lane + 32] = a1[j];
        }
    }
}

__global__ __launch_bounds__(DH)
void reduce_attn_kernel(const int* __restrict__ elist, const int* __restrict__ nep,
                        const float* __restrict__ part_ml,
                        const float* __restrict__ part_acc,
                        __nv_bfloat16* __restrict__ ctx_h,
                        __nv_bfloat16* __restrict__ ctx_l) {
    int e = blockIdx.x, h = blockIdx.y;
    int ne = nep[0]; if (ne > MAXE) ne = MAXE;
    if (e >= ne) return;
    int d = threadIdx.x;
    __shared__ float wsh[NSPLIT];
    __shared__ float Lsh;
    if (d == 0) {
        float M = -1e30f;
        size_t mb = ((size_t)e * NH + h) * NSPLIT;
        for (int s = 0; s < NSPLIT; s++) {
            float m = part_ml[(mb + s) * 2];
            if (m > M) M = m;
        }
        float L = 0.f;
        for (int s = 0; s < NSPLIT; s++) {
            float m = part_ml[(mb + s) * 2];
            float l = part_ml[(mb + s) * 2 + 1];
            float w = __expf(m - M);
            wsh[s] = w;
            L += w * l;
        }
        Lsh = L;
    }
    __syncthreads();
    float acc = 0.f;
    size_t ab = ((size_t)e * NH + h) * NSPLIT;
    for (int s = 0; s < NSPLIT; s++) acc += wsh[s] * part_acc[(ab + s) * DH + d];
    int ft = elist[e];
    store_split(ctx_h, ctx_l, (size_t)ft * D + h * DH + d, acc / Lsh);
}

// ---------------------------------------------------------------------------
extern "C" void kernel_launch(void* const* d_in, const int* in_sizes, int n_in,
                              void* d_out, int out_size) {
    const float* x_qk = (const float*)d_in[0];
    const float* x_v = (const float*)d_in[1];
    const int* qm = (const int*)d_in[2];
    const int* ids = (const int*)d_in[3];
    const int* padp = (const int*)d_in[4];
    const float* Wq = (const float*)d_in[5];
    const float* bq = (const float*)d_in[6];
    const float* Wk = (const float*)d_in[7];
    const float* bk = (const float*)d_in[8];
    const float* Wv = (const float*)d_in[9];
    const float* bv = (const float*)d_in[10];
    const float* Wo = (const float*)d_in[11];
    const float* bo = (const float*)d_in[12];

    int n = in_sizes[0] / D;
    int f = out_size / D;

    float *pk, *pv, *pq, *pml, *pacc;
    int *pidx, *prank, *pelist, *pne;
    unsigned char* pnp;
    cudaGetSymbolAddress((void**)&pk, g_k);
    cudaGetSymbolAddress((void**)&pv, g_v);
    cudaGetSymbolAddress((void**)&pq, g_q);
    cudaGetSymbolAddress((void**)&pidx, g_idx);
    cudaGetSymbolAddress((void**)&pnp, g_npad);
    cudaGetSymbolAddress((void**)&prank, g_rank);
    cudaGetSymbolAddress((void**)&pelist, g_elist);
    cudaGetSymbolAddress((void**)&pne, g_ne);
    cudaGetSymbolAddress((void**)&pml, g_part_ml);
    cudaGetSymbolAddress((void**)&pacc, g_part_acc);

    __nv_bfloat16 *xqk_h, *xqk_l, *xv_h, *xv_l, *ctx_h, *ctx_l;
    __nv_bfloat16 *wk_h, *wk_l, *wv_h, *wv_l, *wq_h, *wq_l, *wo_h, *wo_l;
    cudaGetSymbolAddress((void**)&xqk_h, g_xqk_h);
    cudaGetSymbolAddress((void**)&xqk_l, g_xqk_l);
    cudaGetSymbolAddress((void**)&xv_h, g_xv_h);
    cudaGetSymbolAddress((void**)&xv_l, g_xv_l);
    cudaGetSymbolAddress((void**)&ctx_h, g_ctx_h);
    cudaGetSymbolAddress((void**)&ctx_l, g_ctx_l);
    cudaGetSymbolAddress((void**)&wk_h, g_wk_h);
    cudaGetSymbolAddress((void**)&wk_l, g_wk_l);
    cudaGetSymbolAddress((void**)&wv_h, g_wv_h);
    cudaGetSymbolAddress((void**)&wv_l, g_wv_l);
    cudaGetSymbolAddress((void**)&wq_h, g_wq_h);
    cudaGetSymbolAddress((void**)&wq_l, g_wq_l);
    cudaGetSymbolAddress((void**)&wo_h, g_wo_h);
    cudaGetSymbolAddress((void**)&wo_l, g_wo_l);

    // one-time resources (created outside capture on the correctness call;
    // reused identically on every call -> deterministic work)
    static cudaStream_t s1 = nullptr, s2 = nullptr;
    static cudaEvent_t e0 = nullptr, e1 = nullptr, e2 = nullptr, e3 = nullptr;
    if (!s1) {
        cudaStreamCreateWithFlags(&s1, cudaStreamNonBlocking);
        cudaStreamCreateWithFlags(&s2, cudaStreamNonBlocking);
        cudaEventCreateWithFlags(&e0, cudaEventDisableTiming);
        cudaEventCreateWithFlags(&e1, cudaEventDisableTiming);
        cudaEventCreateWithFlags(&e2, cudaEventDisableTiming);
        cudaEventCreateWithFlags(&e3, cudaEventDisableTiming);
    }

    // 1. fork: prep (s1) parallel with split_multi (main)
    cudaEventRecord(e0, 0);
    cudaStreamWaitEvent(s1, e0, 0);
    prep_kernel<<<1, 256, 0, s1>>>(qm, ids, padp, n, f, pidx, pnp, prank, pelist, pne);
    cudaEventRecord(e1, s1);

    int nx4 = n * D / 4;
    int nw4 = D * D / 4;
    SplitJobs J;
    J.src[0] = (const float4*)x_qk; J.hi[0] = (uint2*)xqk_h; J.lo[0] = (uint2*)xqk_l;
    J.src[1] = (const float4*)x_v;  J.hi[1] = (uint2*)xv_h;  J.lo[1] = (uint2*)xv_l;
    J.src[2] = (const float4*)Wk;   J.hi[2] = (uint2*)wk_h;  J.lo[2] = (uint2*)wk_l;
    J.src[3] = (const float4*)Wv;   J.hi[3] = (uint2*)wv_h;  J.lo[3] = (uint2*)wv_l;
    J.src[4] = (const float4*)Wq;   J.hi[4] = (uint2*)wq_h;  J.lo[4] = (uint2*)wq_l;
    J.src[5] = (const float4*)Wo;   J.hi[5] = (uint2*)wo_h;  J.lo[5] = (uint2*)wo_l;
    J.start[0] = 0;
    J.start[1] = nx4;
    J.start[2] = 2 * nx4;
    J.start[3] = 2 * nx4 + nw4;
    J.start[4] = 2 * nx4 + 2 * nw4;
    J.start[5] = 2 * nx4 + 3 * nw4;
    J.start[6] = 2 * nx4 + 4 * nw4;
    split_multi_kernel<<<(J.start[6] + 255) / 256, 256>>>(J);

    // join prep before GEMM (Q path needs pidx)
    cudaStreamWaitEvent(0, e1, 0);

    // 2. fused K + V + Q GEMM
    const int smem128 = 3 * (128 + 128) * 128;  // 98304 B
    const int smem64 = 3 * (64 + 128) * 128;    // 73728 B
    cudaFuncSetAttribute(gemm_mma_bf<128>, cudaFuncAttributeMaxDynamicSharedMemorySize, smem128);
    cudaFuncSetAttribute(gemm_mma_bf<64>, cudaFuncAttributeMaxDynamicSharedMemorySize, smem64);
    GArg gK = {xqk_h, xqk_l, wk_h, wk_l, bk, pk, n, nullptr};
    GArg gV = {xv_h, xv_l, wv_h, wv_l, bv, pv, n, nullptr};
    GArg gQ = {xqk_h, xqk_l, wq_h, wq_l, bq, pq, f, pidx};
    gemm_mma_bf<128><<<dim3(D / 128, (n + 127) / 128, 3), 256, smem128>>>(gK, gV, gQ, D, D);
    cudaEventRecord(e2, 0);

    // 3. fork: split_attn + reduce (s2) parallel with attn (main)
    cudaStreamWaitEvent(s2, e2, 0);
    split_attn_kernel<<<NSPLIT, NH * 32, 0, s2>>>(pq, pk, pv, pelist, pne, pml, pacc, n);
    reduce_attn_kernel<<<dim3(MAXE, NH), DH, 0, s2>>>(pelist, pne, pml, pacc, ctx_h, ctx_l);
    cudaEventRecord(e3, s2);

    attn_kernel<<<(f * NH + 7) / 8, 256>>>(pq, pk, pv, pidx, pnp, prank,
                                           ctx_h, ctx_l, n, f);

    // join before O GEMM
    cudaStreamWaitEvent(0, e3, 0);

    // 4. O GEMM
    GArg gO = {ctx_h, ctx_l, wo_h, wo_l, bo, (float*)d_out, f, nullptr};
    gemm_mma_bf<64><<<dim3(D / 128, (f + 63) / 64, 1), 256, smem64>>>(gO, gO, gO, D, D);
}